// round 1
// baseline (speedup 1.0000x reference)
#include <cuda_runtime.h>
#include <cuda_bf16.h>

#define N_NODES 100000
#define N_EDGES 1600000
#define NFEAT 256
#define NHID 128
#define NCLASS 40

// Scratch (device globals — no allocation allowed)
__device__ float g_bufA[(size_t)N_NODES * NHID];   // 51.2 MB
__device__ float g_bufB[(size_t)N_NODES * NHID];   // 51.2 MB
__device__ float g_bufC[(size_t)N_NODES * NCLASS]; // 16 MB

// ---------------------------------------------------------------------------
// Tiled GEMM: C[N, FOUT] = A[N, FIN] @ W[FIN, FOUT]
// Block: (FOUT, G) threads; each thread owns TR rows of one output column.
// A tile staged in shared; W streamed via coalesced LDG (L1-resident, 128KB max).
// ---------------------------------------------------------------------------
template<int FIN, int FOUT, int G, int TR>
__global__ void gemm_kernel(const float* __restrict__ A,
                            const float* __restrict__ W,
                            float* __restrict__ C) {
    constexpr int BM = G * TR;
    constexpr int NT = FOUT * G;
    __shared__ float sA[BM * FIN];

    const int col  = threadIdx.x;                 // 0..FOUT-1
    const int g    = threadIdx.y;                 // 0..G-1
    const int row0 = blockIdx.x * BM;
    const int tid  = threadIdx.y * FOUT + threadIdx.x;

    // Cooperative vectorized load of the A tile
    const float4* A4  = reinterpret_cast<const float4*>(A + (size_t)row0 * FIN);
    float4*       sA4 = reinterpret_cast<float4*>(sA);
    constexpr int NV = BM * FIN / 4;
    #pragma unroll 4
    for (int i = tid; i < NV; i += NT) sA4[i] = __ldg(A4 + i);
    __syncthreads();

    float acc[TR];
    #pragma unroll
    for (int r = 0; r < TR; r++) acc[r] = 0.f;

    const float* Wp = W + col;
    #pragma unroll 4
    for (int k = 0; k < FIN; k++) {
        const float w = __ldg(Wp + (size_t)k * FOUT);
        #pragma unroll
        for (int r = 0; r < TR; r++)
            acc[r] += sA[(g * TR + r) * FIN + k] * w;
    }

    #pragma unroll
    for (int r = 0; r < TR; r++) {
        const int row = row0 + g * TR + r;
        C[(size_t)row * FOUT + col] = acc[r];
    }
}

// ---------------------------------------------------------------------------
// Edge scatter, F = 128: one warp per edge. Lane l handles float4 chunk l.
// agg[dst] += ev * S[src]
// ---------------------------------------------------------------------------
__global__ void scatter128_kernel(const float* __restrict__ S,
                                  const int* __restrict__ src,
                                  const int* __restrict__ dst,
                                  const float* __restrict__ ev,
                                  float* __restrict__ agg) {
    const int t    = blockIdx.x * blockDim.x + threadIdx.x;
    const int e    = t >> 5;
    const int lane = t & 31;
    if (e >= N_EDGES) return;
    const int   s = __ldg(src + e);
    const int   d = __ldg(dst + e);
    const float v = __ldg(ev + e);
    const float4 x = __ldg(reinterpret_cast<const float4*>(S) + (size_t)s * 32 + lane);
    float* out = agg + (size_t)d * 128 + lane * 4;
    atomicAdd(out + 0, v * x.x);
    atomicAdd(out + 1, v * x.y);
    atomicAdd(out + 2, v * x.z);
    atomicAdd(out + 3, v * x.w);
}

// ---------------------------------------------------------------------------
// Edge scatter, F = 40: thread handles one float4 chunk (10 per edge).
// ---------------------------------------------------------------------------
__global__ void scatter40_kernel(const float* __restrict__ S,
                                 const int* __restrict__ src,
                                 const int* __restrict__ dst,
                                 const float* __restrict__ ev,
                                 float* __restrict__ agg) {
    const unsigned t = blockIdx.x * blockDim.x + threadIdx.x;
    const unsigned e = t / 10u;
    const unsigned c = t % 10u;
    if (e >= N_EDGES) return;
    const int   s = __ldg(src + e);
    const int   d = __ldg(dst + e);
    const float v = __ldg(ev + e);
    const float4 x = __ldg(reinterpret_cast<const float4*>(S) + (size_t)s * 10 + c);
    float* out = agg + (size_t)d * 40 + c * 4;
    atomicAdd(out + 0, v * x.x);
    atomicAdd(out + 1, v * x.y);
    atomicAdd(out + 2, v * x.z);
    atomicAdd(out + 3, v * x.w);
}

// ---------------------------------------------------------------------------
// In-place h = relu(h + b), F = 128
// ---------------------------------------------------------------------------
__global__ void bias_relu_kernel(float* __restrict__ h, const float* __restrict__ b) {
    const size_t i = (size_t)blockIdx.x * blockDim.x + threadIdx.x;
    if (i >= (size_t)N_NODES * NHID) return;
    h[i] = fmaxf(h[i] + __ldg(b + (i & (NHID - 1))), 0.f);
}

// ---------------------------------------------------------------------------
// In-place log_softmax(row + b3) over 40 classes: one warp per row.
// ---------------------------------------------------------------------------
__global__ void logsoftmax_kernel(float* __restrict__ out, const float* __restrict__ b) {
    const int warp = threadIdx.x >> 5;
    const int lane = threadIdx.x & 31;
    const int row  = blockIdx.x * 8 + warp;
    if (row >= N_NODES) return;
    float* p = out + (size_t)row * NCLASS;

    const float NEG_INF = __int_as_float(0xff800000);
    float v0 = p[lane] + __ldg(b + lane);                                  // lanes 0..31
    float v1 = (lane < 8) ? (p[32 + lane] + __ldg(b + 32 + lane)) : NEG_INF;

    float m = fmaxf(v0, v1);
    #pragma unroll
    for (int o = 16; o; o >>= 1) m = fmaxf(m, __shfl_xor_sync(0xffffffffu, m, o));

    float s = expf(v0 - m) + ((lane < 8) ? expf(v1 - m) : 0.f);
    #pragma unroll
    for (int o = 16; o; o >>= 1) s += __shfl_xor_sync(0xffffffffu, s, o);

    const float ls = m + logf(s);
    p[lane] = v0 - ls;
    if (lane < 8) p[32 + lane] = v1 - ls;
}

// ---------------------------------------------------------------------------
extern "C" void kernel_launch(void* const* d_in, const int* in_sizes, int n_in,
                              void* d_out, int out_size) {
    const float* x    = (const float*)d_in[0];
    const int*   esrc = (const int*)  d_in[1];
    const int*   edst = (const int*)  d_in[2];
    const float* ev   = (const float*)d_in[3];
    const float* W1   = (const float*)d_in[4];
    const float* b1   = (const float*)d_in[5];
    const float* W2   = (const float*)d_in[6];
    const float* b2   = (const float*)d_in[7];
    const float* W3   = (const float*)d_in[8];
    const float* b3   = (const float*)d_in[9];
    float* out = (float*)d_out;

    float *bufA, *bufB, *bufC;
    cudaGetSymbolAddress((void**)&bufA, g_bufA);
    cudaGetSymbolAddress((void**)&bufB, g_bufB);
    cudaGetSymbolAddress((void**)&bufC, g_bufC);

    const int scat128_blocks = (N_EDGES * 32) / 256;       // 200000
    const int scat40_blocks  = (N_EDGES * 10) / 256;       // 62500
    const int ew_blocks      = (N_NODES * NHID) / 256;     // 50000

    // ---- Layer 1: support = x @ W1; agg = scatter; h = relu(agg + b1) ----
    gemm_kernel<NFEAT, NHID, 2, 16><<<N_NODES / 32, dim3(NHID, 2)>>>(x, W1, bufA);
    cudaMemsetAsync(bufB, 0, (size_t)N_NODES * NHID * sizeof(float));
    scatter128_kernel<<<scat128_blocks, 256>>>(bufA, esrc, edst, ev, bufB);
    bias_relu_kernel<<<ew_blocks, 256>>>(bufB, b1);

    // ---- Layer 2 ----
    gemm_kernel<NHID, NHID, 2, 16><<<N_NODES / 32, dim3(NHID, 2)>>>(bufB, W2, bufA);
    cudaMemsetAsync(bufB, 0, (size_t)N_NODES * NHID * sizeof(float));
    scatter128_kernel<<<scat128_blocks, 256>>>(bufA, esrc, edst, ev, bufB);
    bias_relu_kernel<<<ew_blocks, 256>>>(bufB, b2);

    // ---- Layer 3: support3 = h @ W3; out = scatter; log_softmax(out + b3) ----
    gemm_kernel<NHID, NCLASS, 8, 2><<<N_NODES / 16, dim3(NCLASS, 8)>>>(bufB, W3, bufC);
    cudaMemsetAsync(out, 0, (size_t)N_NODES * NCLASS * sizeof(float));
    scatter40_kernel<<<scat40_blocks, 256>>>(bufC, esrc, edst, ev, out);
    logsoftmax_kernel<<<(N_NODES + 7) / 8, 256>>>(out, b3);
}

// round 3
// speedup vs baseline: 1.6184x; 1.6184x over previous
#include <cuda_runtime.h>
#include <cuda_bf16.h>

#define N_NODES 100000
#define N_EDGES 1600000
#define NFEAT 256
#define NHID 128
#define NCLASS 40

// Scratch (device globals — no allocation allowed)
__device__ float g_bufA[(size_t)N_NODES * NHID];   // 51.2 MB
__device__ float g_bufB[(size_t)N_NODES * NHID];   // 51.2 MB
__device__ float g_bufC[(size_t)N_NODES * NCLASS]; // 16 MB

// ---------------------------------------------------------------------------
// Vector reduction: one 16B red.add op instead of 4 scalar atomics.
// ---------------------------------------------------------------------------
__device__ __forceinline__ void red_add_v4(float* p, float a, float b, float c, float d) {
    asm volatile("red.global.add.v4.f32 [%0], {%1, %2, %3, %4};"
                 :: "l"(p), "f"(a), "f"(b), "f"(c), "f"(d) : "memory");
}

// ---------------------------------------------------------------------------
// GEMM with 2-column register tiling: C[N, FOUT] = (relu?)(A)[N, FIN] @ W
// Block: (FOUT/2, G); thread owns TR rows x 2 cols. 16 LDS feed 32 FFMA.
// ---------------------------------------------------------------------------
template<int FIN, int FOUT, int G, int TR, bool RELU>
__global__ void gemm2c_kernel(const float* __restrict__ A,
                              const float* __restrict__ W,
                              float* __restrict__ C) {
    constexpr int BX = FOUT / 2;
    constexpr int BM = G * TR;
    constexpr int NT = BX * G;
    __shared__ float sA[BM * FIN];

    const int tx   = threadIdx.x;                 // 0..BX-1
    const int ty   = threadIdx.y;                 // 0..G-1
    const int row0 = blockIdx.x * BM;
    const int tid  = ty * BX + tx;

    // Cooperative vectorized load of the A tile (+ optional fused ReLU)
    const float4* A4  = reinterpret_cast<const float4*>(A + (size_t)row0 * FIN);
    float4*       sA4 = reinterpret_cast<float4*>(sA);
    constexpr int NV = BM * FIN / 4;
    #pragma unroll 4
    for (int i = tid; i < NV; i += NT) {
        float4 v = __ldg(A4 + i);
        if (RELU) {
            v.x = fmaxf(v.x, 0.f); v.y = fmaxf(v.y, 0.f);
            v.z = fmaxf(v.z, 0.f); v.w = fmaxf(v.w, 0.f);
        }
        sA4[i] = v;
    }
    __syncthreads();

    float acc0[TR], acc1[TR];
    #pragma unroll
    for (int r = 0; r < TR; r++) { acc0[r] = 0.f; acc1[r] = 0.f; }

    #pragma unroll 4
    for (int k = 0; k < FIN; k++) {
        const float w0 = __ldg(W + (size_t)k * FOUT + tx);
        const float w1 = __ldg(W + (size_t)k * FOUT + tx + BX);
        #pragma unroll
        for (int r = 0; r < TR; r++) {
            const float a = sA[(ty * TR + r) * FIN + k];
            acc0[r] += a * w0;
            acc1[r] += a * w1;
        }
    }

    #pragma unroll
    for (int r = 0; r < TR; r++) {
        const int row = row0 + ty * TR + r;
        C[(size_t)row * FOUT + tx]      = acc0[r];
        C[(size_t)row * FOUT + tx + BX] = acc1[r];
    }
}

// ---------------------------------------------------------------------------
// Small GEMM for layer 3 (FOUT=40), single-column threads, fused ReLU on A.
// ---------------------------------------------------------------------------
template<int FIN, int FOUT, int G, int TR, bool RELU>
__global__ void gemm_small_kernel(const float* __restrict__ A,
                                  const float* __restrict__ W,
                                  float* __restrict__ C) {
    constexpr int BM = G * TR;
    constexpr int NT = FOUT * G;
    __shared__ float sA[BM * FIN];

    const int col  = threadIdx.x;
    const int g    = threadIdx.y;
    const int row0 = blockIdx.x * BM;
    const int tid  = threadIdx.y * FOUT + threadIdx.x;

    const float4* A4  = reinterpret_cast<const float4*>(A + (size_t)row0 * FIN);
    float4*       sA4 = reinterpret_cast<float4*>(sA);
    constexpr int NV = BM * FIN / 4;
    for (int i = tid; i < NV; i += NT) {
        float4 v = __ldg(A4 + i);
        if (RELU) {
            v.x = fmaxf(v.x, 0.f); v.y = fmaxf(v.y, 0.f);
            v.z = fmaxf(v.z, 0.f); v.w = fmaxf(v.w, 0.f);
        }
        sA4[i] = v;
    }
    __syncthreads();

    float acc[TR];
    #pragma unroll
    for (int r = 0; r < TR; r++) acc[r] = 0.f;

    #pragma unroll 4
    for (int k = 0; k < FIN; k++) {
        const float w = __ldg(W + (size_t)k * FOUT + col);
        #pragma unroll
        for (int r = 0; r < TR; r++)
            acc[r] += sA[(g * TR + r) * FIN + k] * w;
    }

    #pragma unroll
    for (int r = 0; r < TR; r++)
        C[(size_t)(row0 + g * TR + r) * FOUT + col] = acc[r];
}

// ---------------------------------------------------------------------------
// Edge scatter, F = 128: one warp per edge, one red.v4 per lane.
// ---------------------------------------------------------------------------
__global__ void scatter128_kernel(const float* __restrict__ S,
                                  const int* __restrict__ src,
                                  const int* __restrict__ dst,
                                  const float* __restrict__ ev,
                                  float* __restrict__ agg) {
    const int t    = blockIdx.x * blockDim.x + threadIdx.x;
    const int e    = t >> 5;
    const int lane = t & 31;
    if (e >= N_EDGES) return;
    const int   s = __ldg(src + e);
    const int   d = __ldg(dst + e);
    const float v = __ldg(ev + e);
    const float4 x = __ldg(reinterpret_cast<const float4*>(S) + (size_t)s * 32 + lane);
    red_add_v4(agg + (size_t)d * 128 + lane * 4, v * x.x, v * x.y, v * x.z, v * x.w);
}

// ---------------------------------------------------------------------------
// Edge scatter, F = 40: thread handles one float4 chunk (10 per edge).
// ---------------------------------------------------------------------------
__global__ void scatter40_kernel(const float* __restrict__ S,
                                 const int* __restrict__ src,
                                 const int* __restrict__ dst,
                                 const float* __restrict__ ev,
                                 float* __restrict__ agg) {
    const unsigned t = blockIdx.x * blockDim.x + threadIdx.x;
    const unsigned e = t / 10u;
    const unsigned c = t % 10u;
    if (e >= N_EDGES) return;
    const int   s = __ldg(src + e);
    const int   d = __ldg(dst + e);
    const float v = __ldg(ev + e);
    const float4 x = __ldg(reinterpret_cast<const float4*>(S) + (size_t)s * 10 + c);
    red_add_v4(agg + (size_t)d * 40 + c * 4, v * x.x, v * x.y, v * x.z, v * x.w);
}

// ---------------------------------------------------------------------------
// Initialize agg buffer with broadcast bias (replaces memset + bias add)
// ---------------------------------------------------------------------------
__global__ void bias_init128_kernel(float* __restrict__ h, const float* __restrict__ b) {
    const size_t i = (size_t)blockIdx.x * blockDim.x + threadIdx.x;
    if (i < (size_t)N_NODES * NHID)
        h[i] = __ldg(b + (i & (NHID - 1)));
}

__global__ void bias_init40_kernel(float* __restrict__ h, const float* __restrict__ b) {
    const size_t i = (size_t)blockIdx.x * blockDim.x + threadIdx.x;
    if (i < (size_t)N_NODES * NCLASS)
        h[i] = __ldg(b + (i % NCLASS));
}

// ---------------------------------------------------------------------------
// In-place log_softmax over 40 classes (bias already baked in): warp per row.
// ---------------------------------------------------------------------------
__global__ void logsoftmax_kernel(float* __restrict__ out) {
    const int warp = threadIdx.x >> 5;
    const int lane = threadIdx.x & 31;
    const int row  = blockIdx.x * 8 + warp;
    if (row >= N_NODES) return;
    float* p = out + (size_t)row * NCLASS;

    const float NEG_INF = __int_as_float(0xff800000);
    float v0 = p[lane];
    float v1 = (lane < 8) ? p[32 + lane] : NEG_INF;

    float m = fmaxf(v0, v1);
    #pragma unroll
    for (int o = 16; o; o >>= 1) m = fmaxf(m, __shfl_xor_sync(0xffffffffu, m, o));

    float s = expf(v0 - m) + ((lane < 8) ? expf(v1 - m) : 0.f);
    #pragma unroll
    for (int o = 16; o; o >>= 1) s += __shfl_xor_sync(0xffffffffu, s, o);

    const float ls = m + logf(s);
    p[lane] = v0 - ls;
    if (lane < 8) p[32 + lane] = v1 - ls;
}

// ---------------------------------------------------------------------------
extern "C" void kernel_launch(void* const* d_in, const int* in_sizes, int n_in,
                              void* d_out, int out_size) {
    const float* x    = (const float*)d_in[0];
    const int*   esrc = (const int*)  d_in[1];
    const int*   edst = (const int*)  d_in[2];
    const float* ev   = (const float*)d_in[3];
    const float* W1   = (const float*)d_in[4];
    const float* b1   = (const float*)d_in[5];
    const float* W2   = (const float*)d_in[6];
    const float* b2   = (const float*)d_in[7];
    const float* W3   = (const float*)d_in[8];
    const float* b3   = (const float*)d_in[9];
    float* out = (float*)d_out;

    float *bufA, *bufB, *bufC;
    cudaGetSymbolAddress((void**)&bufA, g_bufA);
    cudaGetSymbolAddress((void**)&bufB, g_bufB);
    cudaGetSymbolAddress((void**)&bufC, g_bufC);

    const int scat128_blocks = (N_EDGES * 32) / 256;           // 200000
    const int scat40_blocks  = (N_EDGES * 10 + 255) / 256;
    const int ew128_blocks   = (N_NODES * NHID) / 256;         // 50000
    const int ew40_blocks    = (N_NODES * NCLASS + 255) / 256;

    // ---- Layer 1: support1 = x @ W1 -> bufA; agg1+b1 -> bufB ----
    gemm2c_kernel<NFEAT, NHID, 4, 8, false><<<N_NODES / 32, dim3(NHID / 2, 4)>>>(x, W1, bufA);
    bias_init128_kernel<<<ew128_blocks, 256>>>(bufB, b1);
    scatter128_kernel<<<scat128_blocks, 256>>>(bufA, esrc, edst, ev, bufB);

    // ---- Layer 2: support2 = relu(bufB) @ W2 -> bufA; agg2+b2 -> bufB ----
    gemm2c_kernel<NHID, NHID, 4, 8, true><<<N_NODES / 32, dim3(NHID / 2, 4)>>>(bufB, W2, bufA);
    bias_init128_kernel<<<ew128_blocks, 256>>>(bufB, b2);
    scatter128_kernel<<<scat128_blocks, 256>>>(bufA, esrc, edst, ev, bufB);

    // ---- Layer 3: support3 = relu(bufB) @ W3 -> bufC; agg3+b3 -> out ----
    gemm_small_kernel<NHID, NCLASS, 8, 2, true><<<N_NODES / 16, dim3(NCLASS, 8)>>>(bufB, W3, bufC);
    bias_init40_kernel<<<ew40_blocks, 256>>>(out, b3);
    scatter40_kernel<<<scat40_blocks, 256>>>(bufC, esrc, edst, ev, out);
    logsoftmax_kernel<<<(N_NODES + 7) / 8, 256>>>(out);
}

// round 4
// speedup vs baseline: 1.9932x; 1.2316x over previous
#include <cuda_runtime.h>
#include <cuda_bf16.h>

#define N_NODES 100000
#define N_EDGES 1600000
#define NFEAT 256
#define NHID 128
#define NCLASS 40
#define SCAN_BS 1024
#define NB ((N_NODES + SCAN_BS - 1) / SCAN_BS)   // 98

// Scratch (device globals — no allocation allowed)
__device__ float g_bufA[(size_t)N_NODES * NHID];   // 51.2 MB
__device__ float g_bufB[(size_t)N_NODES * NHID];   // 51.2 MB
__device__ float g_bufC[(size_t)N_NODES * NCLASS]; // 16 MB
__device__ int   g_deg[N_NODES];
__device__ int   g_off[N_NODES + 1];
__device__ int   g_cursor[N_NODES];
__device__ int   g_bsum[SCAN_BS];
__device__ int   g_csr_src[N_EDGES];
__device__ float g_csr_val[N_EDGES];

// ---------------------------------------------------------------------------
// GEMM with 2-column register tiling (at the sm_103a fp32-FFMA floor).
// ---------------------------------------------------------------------------
template<int FIN, int FOUT, int G, int TR, bool RELU>
__global__ void gemm2c_kernel(const float* __restrict__ A,
                              const float* __restrict__ W,
                              float* __restrict__ C) {
    constexpr int BX = FOUT / 2;
    constexpr int BM = G * TR;
    constexpr int NT = BX * G;
    __shared__ float sA[BM * FIN];

    const int tx   = threadIdx.x;
    const int ty   = threadIdx.y;
    const int row0 = blockIdx.x * BM;
    const int tid  = ty * BX + tx;

    const float4* A4  = reinterpret_cast<const float4*>(A + (size_t)row0 * FIN);
    float4*       sA4 = reinterpret_cast<float4*>(sA);
    constexpr int NV = BM * FIN / 4;
    #pragma unroll 4
    for (int i = tid; i < NV; i += NT) {
        float4 v = __ldg(A4 + i);
        if (RELU) {
            v.x = fmaxf(v.x, 0.f); v.y = fmaxf(v.y, 0.f);
            v.z = fmaxf(v.z, 0.f); v.w = fmaxf(v.w, 0.f);
        }
        sA4[i] = v;
    }
    __syncthreads();

    float acc0[TR], acc1[TR];
    #pragma unroll
    for (int r = 0; r < TR; r++) { acc0[r] = 0.f; acc1[r] = 0.f; }

    #pragma unroll 4
    for (int k = 0; k < FIN; k++) {
        const float w0 = __ldg(W + (size_t)k * FOUT + tx);
        const float w1 = __ldg(W + (size_t)k * FOUT + tx + BX);
        #pragma unroll
        for (int r = 0; r < TR; r++) {
            const float a = sA[(ty * TR + r) * FIN + k];
            acc0[r] += a * w0;
            acc1[r] += a * w1;
        }
    }

    #pragma unroll
    for (int r = 0; r < TR; r++) {
        const int row = row0 + ty * TR + r;
        C[(size_t)row * FOUT + tx]      = acc0[r];
        C[(size_t)row * FOUT + tx + BX] = acc1[r];
    }
}

// ---------------------------------------------------------------------------
// Small GEMM for layer 3 (FOUT=40), fused ReLU on A.
// ---------------------------------------------------------------------------
template<int FIN, int FOUT, int G, int TR, bool RELU>
__global__ void gemm_small_kernel(const float* __restrict__ A,
                                  const float* __restrict__ W,
                                  float* __restrict__ C) {
    constexpr int BM = G * TR;
    constexpr int NT = FOUT * G;
    __shared__ float sA[BM * FIN];

    const int col  = threadIdx.x;
    const int g    = threadIdx.y;
    const int row0 = blockIdx.x * BM;
    const int tid  = threadIdx.y * FOUT + threadIdx.x;

    const float4* A4  = reinterpret_cast<const float4*>(A + (size_t)row0 * FIN);
    float4*       sA4 = reinterpret_cast<float4*>(sA);
    constexpr int NV = BM * FIN / 4;
    for (int i = tid; i < NV; i += NT) {
        float4 v = __ldg(A4 + i);
        if (RELU) {
            v.x = fmaxf(v.x, 0.f); v.y = fmaxf(v.y, 0.f);
            v.z = fmaxf(v.z, 0.f); v.w = fmaxf(v.w, 0.f);
        }
        sA4[i] = v;
    }
    __syncthreads();

    float acc[TR];
    #pragma unroll
    for (int r = 0; r < TR; r++) acc[r] = 0.f;

    #pragma unroll 4
    for (int k = 0; k < FIN; k++) {
        const float w = __ldg(W + (size_t)k * FOUT + col);
        #pragma unroll
        for (int r = 0; r < TR; r++)
            acc[r] += sA[(g * TR + r) * FIN + k] * w;
    }

    #pragma unroll
    for (int r = 0; r < TR; r++)
        C[(size_t)(row0 + g * TR + r) * FOUT + col] = acc[r];
}

// ---------------------------------------------------------------------------
// CSR build: histogram -> block scan -> scan of block sums -> add -> fill
// ---------------------------------------------------------------------------
__global__ void hist_kernel(const int* __restrict__ dst, int* __restrict__ deg) {
    const int e = blockIdx.x * blockDim.x + threadIdx.x;
    if (e < N_EDGES) atomicAdd(deg + __ldg(dst + e), 1);
}

__global__ void scan_block_kernel(const int* __restrict__ deg,
                                  int* __restrict__ off,
                                  int* __restrict__ bsum) {
    __shared__ int sh[SCAN_BS];
    const int tid = threadIdx.x;
    const int i   = blockIdx.x * SCAN_BS + tid;
    const int v   = (i < N_NODES) ? deg[i] : 0;
    sh[tid] = v;
    __syncthreads();
    #pragma unroll
    for (int o = 1; o < SCAN_BS; o <<= 1) {
        const int add = (tid >= o) ? sh[tid - o] : 0;
        __syncthreads();
        sh[tid] += add;
        __syncthreads();
    }
    if (i < N_NODES) off[i] = sh[tid] - v;            // exclusive within block
    if (tid == SCAN_BS - 1) bsum[blockIdx.x] = sh[tid];
}

__global__ void scan_sums_kernel(int* __restrict__ bsum) {
    __shared__ int sh[128];
    const int tid = threadIdx.x;
    const int v = (tid < NB) ? bsum[tid] : 0;
    sh[tid] = v;
    __syncthreads();
    #pragma unroll
    for (int o = 1; o < 128; o <<= 1) {
        const int add = (tid >= o) ? sh[tid - o] : 0;
        __syncthreads();
        sh[tid] += add;
        __syncthreads();
    }
    if (tid < NB) bsum[tid] = sh[tid] - v;            // exclusive
}

__global__ void scan_add_kernel(int* __restrict__ off, const int* __restrict__ bsum) {
    const int i = blockIdx.x * blockDim.x + threadIdx.x;
    if (i < N_NODES) off[i] += __ldg(bsum + blockIdx.x * SCAN_BS / blockDim.x + 0 * i);
    if (i == 0) off[N_NODES] = N_EDGES;
}

// (scan_add above must index bsum by element block; fix via dedicated version)
__global__ void scan_add2_kernel(int* __restrict__ off, const int* __restrict__ bsum) {
    const int i = blockIdx.x * blockDim.x + threadIdx.x;
    if (i < N_NODES) off[i] += __ldg(bsum + (i / SCAN_BS));
    if (i == 0) off[N_NODES] = N_EDGES;
}

__global__ void csr_fill_kernel(const int* __restrict__ src,
                                const int* __restrict__ dst,
                                const float* __restrict__ ev,
                                int* __restrict__ cursor,
                                int* __restrict__ csr_s,
                                float* __restrict__ csr_v) {
    const int e = blockIdx.x * blockDim.x + threadIdx.x;
    if (e >= N_EDGES) return;
    const int d = __ldg(dst + e);
    const int p = atomicAdd(cursor + d, 1);
    csr_s[p] = __ldg(src + e);
    csr_v[p] = __ldg(ev + e);
}

// ---------------------------------------------------------------------------
// Pull-mode aggregation, F = 128: one block (128 thr) per node.
// agg[d][t] = bias[t] + sum_e csr_v[e] * S[csr_s[e]][t]
// ---------------------------------------------------------------------------
__global__ void gather128_kernel(const float* __restrict__ S,
                                 const int* __restrict__ off,
                                 const int* __restrict__ csr_s,
                                 const float* __restrict__ csr_v,
                                 const float* __restrict__ bias,
                                 float* __restrict__ agg) {
    const int d = blockIdx.x;
    const int t = threadIdx.x;
    const int beg = __ldg(off + d);
    const int end = __ldg(off + d + 1);
    float acc = __ldg(bias + t);
    int i = beg;
    for (; i + 4 <= end; i += 4) {
        const int   s0 = __ldg(csr_s + i),     s1 = __ldg(csr_s + i + 1);
        const int   s2 = __ldg(csr_s + i + 2), s3 = __ldg(csr_s + i + 3);
        const float v0 = __ldg(csr_v + i),     v1 = __ldg(csr_v + i + 1);
        const float v2 = __ldg(csr_v + i + 2), v3 = __ldg(csr_v + i + 3);
        const float x0 = __ldg(S + (size_t)s0 * NHID + t);
        const float x1 = __ldg(S + (size_t)s1 * NHID + t);
        const float x2 = __ldg(S + (size_t)s2 * NHID + t);
        const float x3 = __ldg(S + (size_t)s3 * NHID + t);
        acc += v0 * x0 + v1 * x1 + v2 * x2 + v3 * x3;
    }
    for (; i < end; i++)
        acc += __ldg(csr_v + i) * __ldg(S + (size_t)__ldg(csr_s + i) * NHID + t);
    agg[(size_t)d * NHID + t] = acc;
}

// ---------------------------------------------------------------------------
// Pull-mode aggregation, F = 40: one block (64 thr, 40 active) per node.
// ---------------------------------------------------------------------------
__global__ void gather40_kernel(const float* __restrict__ S,
                                const int* __restrict__ off,
                                const int* __restrict__ csr_s,
                                const float* __restrict__ csr_v,
                                const float* __restrict__ bias,
                                float* __restrict__ agg) {
    const int d = blockIdx.x;
    const int t = threadIdx.x;
    if (t >= NCLASS) return;
    const int beg = __ldg(off + d);
    const int end = __ldg(off + d + 1);
    float acc = __ldg(bias + t);
    int i = beg;
    for (; i + 4 <= end; i += 4) {
        const int   s0 = __ldg(csr_s + i),     s1 = __ldg(csr_s + i + 1);
        const int   s2 = __ldg(csr_s + i + 2), s3 = __ldg(csr_s + i + 3);
        const float v0 = __ldg(csr_v + i),     v1 = __ldg(csr_v + i + 1);
        const float v2 = __ldg(csr_v + i + 2), v3 = __ldg(csr_v + i + 3);
        const float x0 = __ldg(S + (size_t)s0 * NCLASS + t);
        const float x1 = __ldg(S + (size_t)s1 * NCLASS + t);
        const float x2 = __ldg(S + (size_t)s2 * NCLASS + t);
        const float x3 = __ldg(S + (size_t)s3 * NCLASS + t);
        acc += v0 * x0 + v1 * x1 + v2 * x2 + v3 * x3;
    }
    for (; i < end; i++)
        acc += __ldg(csr_v + i) * __ldg(S + (size_t)__ldg(csr_s + i) * NCLASS + t);
    agg[(size_t)d * NCLASS + t] = acc;
}

// ---------------------------------------------------------------------------
// In-place log_softmax over 40 classes (bias already baked in): warp per row.
// ---------------------------------------------------------------------------
__global__ void logsoftmax_kernel(float* __restrict__ out) {
    const int warp = threadIdx.x >> 5;
    const int lane = threadIdx.x & 31;
    const int row  = blockIdx.x * 8 + warp;
    if (row >= N_NODES) return;
    float* p = out + (size_t)row * NCLASS;

    const float NEG_INF = __int_as_float(0xff800000);
    float v0 = p[lane];
    float v1 = (lane < 8) ? p[32 + lane] : NEG_INF;

    float m = fmaxf(v0, v1);
    #pragma unroll
    for (int o = 16; o; o >>= 1) m = fmaxf(m, __shfl_xor_sync(0xffffffffu, m, o));

    float s = expf(v0 - m) + ((lane < 8) ? expf(v1 - m) : 0.f);
    #pragma unroll
    for (int o = 16; o; o >>= 1) s += __shfl_xor_sync(0xffffffffu, s, o);

    const float ls = m + logf(s);
    p[lane] = v0 - ls;
    if (lane < 8) p[32 + lane] = v1 - ls;
}

// ---------------------------------------------------------------------------
extern "C" void kernel_launch(void* const* d_in, const int* in_sizes, int n_in,
                              void* d_out, int out_size) {
    const float* x    = (const float*)d_in[0];
    const int*   esrc = (const int*)  d_in[1];
    const int*   edst = (const int*)  d_in[2];
    const float* ev   = (const float*)d_in[3];
    const float* W1   = (const float*)d_in[4];
    const float* b1   = (const float*)d_in[5];
    const float* W2   = (const float*)d_in[6];
    const float* b2   = (const float*)d_in[7];
    const float* W3   = (const float*)d_in[8];
    const float* b3   = (const float*)d_in[9];
    float* out = (float*)d_out;

    float *bufA, *bufB, *bufC, *csrV;
    int *deg, *off, *cursor, *bsum, *csrS;
    cudaGetSymbolAddress((void**)&bufA,   g_bufA);
    cudaGetSymbolAddress((void**)&bufB,   g_bufB);
    cudaGetSymbolAddress((void**)&bufC,   g_bufC);
    cudaGetSymbolAddress((void**)&deg,    g_deg);
    cudaGetSymbolAddress((void**)&off,    g_off);
    cudaGetSymbolAddress((void**)&cursor, g_cursor);
    cudaGetSymbolAddress((void**)&bsum,   g_bsum);
    cudaGetSymbolAddress((void**)&csrS,   g_csr_src);
    cudaGetSymbolAddress((void**)&csrV,   g_csr_val);

    const int edge_blocks = (N_EDGES + 255) / 256;

    // ---- Build CSR by destination (once; reused by all 3 layers) ----
    cudaMemsetAsync(deg, 0, N_NODES * sizeof(int));
    hist_kernel<<<edge_blocks, 256>>>(edst, deg);
    scan_block_kernel<<<NB, SCAN_BS>>>(deg, off, bsum);
    scan_sums_kernel<<<1, 128>>>(bsum);
    scan_add2_kernel<<<(N_NODES + 255) / 256, 256>>>(off, bsum);
    cudaMemcpyAsync(cursor, off, N_NODES * sizeof(int), cudaMemcpyDeviceToDevice);
    csr_fill_kernel<<<edge_blocks, 256>>>(esrc, edst, ev, cursor, csrS, csrV);

    // ---- Layer 1 ----
    gemm2c_kernel<NFEAT, NHID, 4, 8, false><<<N_NODES / 32, dim3(NHID / 2, 4)>>>(x, W1, bufA);
    gather128_kernel<<<N_NODES, NHID>>>(bufA, off, csrS, csrV, b1, bufB);

    // ---- Layer 2 ----
    gemm2c_kernel<NHID, NHID, 4, 8, true><<<N_NODES / 32, dim3(NHID / 2, 4)>>>(bufB, W2, bufA);
    gather128_kernel<<<N_NODES, NHID>>>(bufA, off, csrS, csrV, b2, bufB);

    // ---- Layer 3 ----
    gemm_small_kernel<NHID, NCLASS, 8, 2, true><<<N_NODES / 16, dim3(NCLASS, 8)>>>(bufB, W3, bufC);
    gather40_kernel<<<N_NODES, 64>>>(bufC, off, csrS, csrV, b3, out);
    logsoftmax_kernel<<<(N_NODES + 7) / 8, 256>>>(out);
}

// round 5
// speedup vs baseline: 2.4373x; 1.2228x over previous
#include <cuda_runtime.h>
#include <cuda_bf16.h>
#include <cstdint>

#define N_NODES 100000
#define N_EDGES 1600000
#define NFEAT 256
#define NHID 128
#define NCLASS 40
#define SCAN_BS 1024
#define NB ((N_NODES + SCAN_BS - 1) / SCAN_BS)   // 98

// Scratch (device globals — no allocation allowed)
__device__ float g_bufA[(size_t)N_NODES * NHID];   // 51.2 MB
__device__ float g_bufB[(size_t)N_NODES * NHID];   // 51.2 MB
__device__ float g_bufC[(size_t)N_NODES * NCLASS]; // 16 MB
__device__ int   g_deg[N_NODES];
__device__ int   g_off[N_NODES + 1];
__device__ int   g_cursor[N_NODES];
__device__ int   g_bsum[SCAN_BS];
__device__ int   g_csr_src[N_EDGES];
__device__ float g_csr_val[N_EDGES];

// ---------------------------------------------------------------------------
// tf32 helpers
// ---------------------------------------------------------------------------
__device__ __forceinline__ uint32_t f2tf32(float x) {
    uint32_t r;
    asm("cvt.rna.tf32.f32 %0, %1;" : "=r"(r) : "f"(x));
    return r;
}

__device__ __forceinline__ void mma_tf32(float* d, const uint32_t* a, uint32_t b0, uint32_t b1) {
    asm volatile(
        "mma.sync.aligned.m16n8k8.row.col.f32.tf32.tf32.f32 "
        "{%0,%1,%2,%3}, {%4,%5,%6,%7}, {%8,%9}, {%0,%1,%2,%3};"
        : "+f"(d[0]), "+f"(d[1]), "+f"(d[2]), "+f"(d[3])
        : "r"(a[0]), "r"(a[1]), "r"(a[2]), "r"(a[3]), "r"(b0), "r"(b1));
}

// ---------------------------------------------------------------------------
// Tensor-core GEMM (3xTF32, fp32-accurate): C[N, 128] = (relu?)(A)[N, FIN] @ W
// CTA: 128 rows x 128 cols, 8 warps (4 M x 2 N), warp tile 32x64.
// K streamed in chunks of 16 through conflict-free padded SMEM.
// ---------------------------------------------------------------------------
#define KB 16
#define SA_STRIDE 20    // (20*g + tig) % 32 distinct for g in [0,8), tig in [0,4)
#define SW_STRIDE 136   // (136*tig + g) % 32 distinct

template<int FIN, bool RELU>
__global__ __launch_bounds__(256, 2)
void gemm_tc_kernel(const float* __restrict__ A,
                    const float* __restrict__ W,
                    float* __restrict__ C) {
    __shared__ uint32_t sAh[128 * SA_STRIDE];
    __shared__ uint32_t sAl[128 * SA_STRIDE];
    __shared__ uint32_t sWh[KB * SW_STRIDE];
    __shared__ uint32_t sWl[KB * SW_STRIDE];

    const int tid  = threadIdx.x;
    const int lane = tid & 31;
    const int warp = tid >> 5;
    const int wm   = warp & 3;        // M quadrant (32 rows each)
    const int wn   = warp >> 2;       // N half (64 cols each)
    const int g    = lane >> 2;
    const int tig  = lane & 3;
    const int row0 = blockIdx.x * 128;

    float acc[2][8][4];
    #pragma unroll
    for (int mf = 0; mf < 2; mf++)
        #pragma unroll
        for (int nf = 0; nf < 8; nf++)
            #pragma unroll
            for (int r = 0; r < 4; r++) acc[mf][nf][r] = 0.f;

    constexpr int NCHUNK = FIN / KB;
    for (int kc = 0; kc < NCHUNK; kc++) {
        // ---- cooperative load + relu + tf32 hi/lo split ----
        // A chunk: 128 rows x 16 cols = 512 float4, 2 per thread
        #pragma unroll
        for (int j = 0; j < 2; j++) {
            const int fi  = tid * 2 + j;          // 0..511
            const int r   = fi >> 2;              // 0..127
            const int c4  = (fi & 3) * 4;         // 0,4,8,12
            const int gr  = min(row0 + r, N_NODES - 1);
            float4 v = __ldg(reinterpret_cast<const float4*>(A + (size_t)gr * FIN + kc * KB + c4));
            if (RELU) {
                v.x = fmaxf(v.x, 0.f); v.y = fmaxf(v.y, 0.f);
                v.z = fmaxf(v.z, 0.f); v.w = fmaxf(v.w, 0.f);
            }
            uint32_t* ph = sAh + r * SA_STRIDE + c4;
            uint32_t* pl = sAl + r * SA_STRIDE + c4;
            const float e[4] = {v.x, v.y, v.z, v.w};
            #pragma unroll
            for (int q = 0; q < 4; q++) {
                const uint32_t hb = f2tf32(e[q]);
                ph[q] = hb;
                pl[q] = f2tf32(e[q] - __uint_as_float(hb));
            }
        }
        // W chunk: 16 rows(k) x 128 cols = 512 float4, 2 per thread
        #pragma unroll
        for (int j = 0; j < 2; j++) {
            const int fi = tid * 2 + j;
            const int kr = fi >> 5;               // 0..15
            const int c4 = (fi & 31) * 4;         // 0..124
            float4 v = __ldg(reinterpret_cast<const float4*>(W + (size_t)(kc * KB + kr) * 128 + c4));
            uint32_t* ph = sWh + kr * SW_STRIDE + c4;
            uint32_t* pl = sWl + kr * SW_STRIDE + c4;
            const float e[4] = {v.x, v.y, v.z, v.w};
            #pragma unroll
            for (int q = 0; q < 4; q++) {
                const uint32_t hb = f2tf32(e[q]);
                ph[q] = hb;
                pl[q] = f2tf32(e[q] - __uint_as_float(hb));
            }
        }
        __syncthreads();

        // ---- 2 k-steps of 8 ----
        #pragma unroll
        for (int ks = 0; ks < 2; ks++) {
            const int k0 = ks * 8;
            uint32_t ah[2][4], al[2][4];
            #pragma unroll
            for (int mf = 0; mf < 2; mf++) {
                const int rbase = wm * 32 + mf * 16 + g;
                ah[mf][0] = sAh[(rbase)     * SA_STRIDE + k0 + tig];
                ah[mf][1] = sAh[(rbase + 8) * SA_STRIDE + k0 + tig];
                ah[mf][2] = sAh[(rbase)     * SA_STRIDE + k0 + tig + 4];
                ah[mf][3] = sAh[(rbase + 8) * SA_STRIDE + k0 + tig + 4];
                al[mf][0] = sAl[(rbase)     * SA_STRIDE + k0 + tig];
                al[mf][1] = sAl[(rbase + 8) * SA_STRIDE + k0 + tig];
                al[mf][2] = sAl[(rbase)     * SA_STRIDE + k0 + tig + 4];
                al[mf][3] = sAl[(rbase + 8) * SA_STRIDE + k0 + tig + 4];
            }
            #pragma unroll
            for (int nf = 0; nf < 8; nf++) {
                const int col = wn * 64 + nf * 8 + g;
                const uint32_t bh0 = sWh[(k0 + tig)     * SW_STRIDE + col];
                const uint32_t bh1 = sWh[(k0 + tig + 4) * SW_STRIDE + col];
                const uint32_t bl0 = sWl[(k0 + tig)     * SW_STRIDE + col];
                const uint32_t bl1 = sWl[(k0 + tig + 4) * SW_STRIDE + col];
                #pragma unroll
                for (int mf = 0; mf < 2; mf++) {
                    mma_tf32(acc[mf][nf], ah[mf], bh0, bh1);  // hi*hi
                    mma_tf32(acc[mf][nf], ah[mf], bl0, bl1);  // hi*lo
                    mma_tf32(acc[mf][nf], al[mf], bh0, bh1);  // lo*hi
                }
            }
        }
        __syncthreads();
    }

    // ---- epilogue: float2 stores ----
    #pragma unroll
    for (int mf = 0; mf < 2; mf++) {
        const int r0 = row0 + wm * 32 + mf * 16 + g;
        const int r1 = r0 + 8;
        #pragma unroll
        for (int nf = 0; nf < 8; nf++) {
            const int c = wn * 64 + nf * 8 + tig * 2;
            if (r0 < N_NODES)
                *reinterpret_cast<float2*>(C + (size_t)r0 * 128 + c) =
                    make_float2(acc[mf][nf][0], acc[mf][nf][1]);
            if (r1 < N_NODES)
                *reinterpret_cast<float2*>(C + (size_t)r1 * 128 + c) =
                    make_float2(acc[mf][nf][2], acc[mf][nf][3]);
        }
    }
}

// ---------------------------------------------------------------------------
// Small GEMM for layer 3 (FOUT=40), fused ReLU on A.
// ---------------------------------------------------------------------------
template<int FIN, int FOUT, int G, int TR, bool RELU>
__global__ void gemm_small_kernel(const float* __restrict__ A,
                                  const float* __restrict__ W,
                                  float* __restrict__ C) {
    constexpr int BM = G * TR;
    constexpr int NT = FOUT * G;
    __shared__ float sA[BM * FIN];

    const int col  = threadIdx.x;
    const int g    = threadIdx.y;
    const int row0 = blockIdx.x * BM;
    const int tid  = threadIdx.y * FOUT + threadIdx.x;

    const float4* A4  = reinterpret_cast<const float4*>(A + (size_t)row0 * FIN);
    float4*       sA4 = reinterpret_cast<float4*>(sA);
    constexpr int NV = BM * FIN / 4;
    for (int i = tid; i < NV; i += NT) {
        float4 v = __ldg(A4 + i);
        if (RELU) {
            v.x = fmaxf(v.x, 0.f); v.y = fmaxf(v.y, 0.f);
            v.z = fmaxf(v.z, 0.f); v.w = fmaxf(v.w, 0.f);
        }
        sA4[i] = v;
    }
    __syncthreads();

    float acc[TR];
    #pragma unroll
    for (int r = 0; r < TR; r++) acc[r] = 0.f;

    #pragma unroll 4
    for (int k = 0; k < FIN; k++) {
        const float w = __ldg(W + (size_t)k * FOUT + col);
        #pragma unroll
        for (int r = 0; r < TR; r++)
            acc[r] += sA[(g * TR + r) * FIN + k] * w;
    }

    #pragma unroll
    for (int r = 0; r < TR; r++)
        C[(size_t)(row0 + g * TR + r) * FOUT + col] = acc[r];
}

// ---------------------------------------------------------------------------
// CSR build: histogram -> block scan -> scan of block sums -> add -> fill
// ---------------------------------------------------------------------------
__global__ void hist_kernel(const int* __restrict__ dst, int* __restrict__ deg) {
    const int e = blockIdx.x * blockDim.x + threadIdx.x;
    if (e < N_EDGES) atomicAdd(deg + __ldg(dst + e), 1);
}

__global__ void scan_block_kernel(const int* __restrict__ deg,
                                  int* __restrict__ off,
                                  int* __restrict__ bsum) {
    __shared__ int sh[SCAN_BS];
    const int tid = threadIdx.x;
    const int i   = blockIdx.x * SCAN_BS + tid;
    const int v   = (i < N_NODES) ? deg[i] : 0;
    sh[tid] = v;
    __syncthreads();
    #pragma unroll
    for (int o = 1; o < SCAN_BS; o <<= 1) {
        const int add = (tid >= o) ? sh[tid - o] : 0;
        __syncthreads();
        sh[tid] += add;
        __syncthreads();
    }
    if (i < N_NODES) off[i] = sh[tid] - v;            // exclusive within block
    if (tid == SCAN_BS - 1) bsum[blockIdx.x] = sh[tid];
}

__global__ void scan_sums_kernel(int* __restrict__ bsum) {
    __shared__ int sh[128];
    const int tid = threadIdx.x;
    const int v = (tid < NB) ? bsum[tid] : 0;
    sh[tid] = v;
    __syncthreads();
    #pragma unroll
    for (int o = 1; o < 128; o <<= 1) {
        const int add = (tid >= o) ? sh[tid - o] : 0;
        __syncthreads();
        sh[tid] += add;
        __syncthreads();
    }
    if (tid < NB) bsum[tid] = sh[tid] - v;            // exclusive
}

__global__ void scan_add2_kernel(int* __restrict__ off, const int* __restrict__ bsum) {
    const int i = blockIdx.x * blockDim.x + threadIdx.x;
    if (i < N_NODES) off[i] += __ldg(bsum + (i / SCAN_BS));
    if (i == 0) off[N_NODES] = N_EDGES;
}

__global__ void csr_fill_kernel(const int* __restrict__ src,
                                const int* __restrict__ dst,
                                const float* __restrict__ ev,
                                int* __restrict__ cursor,
                                int* __restrict__ csr_s,
                                float* __restrict__ csr_v) {
    const int e = blockIdx.x * blockDim.x + threadIdx.x;
    if (e >= N_EDGES) return;
    const int d = __ldg(dst + e);
    const int p = atomicAdd(cursor + d, 1);
    csr_s[p] = __ldg(src + e);
    csr_v[p] = __ldg(ev + e);
}

// ---------------------------------------------------------------------------
// Pull-mode aggregation, F = 128: one warp per node, float4 per lane.
// agg[d][:] = bias[:] + sum_e csr_v[e] * S[csr_s[e]][:]
// ---------------------------------------------------------------------------
__global__ void gather128_kernel(const float* __restrict__ S,
                                 const int* __restrict__ off,
                                 const int* __restrict__ csr_s,
                                 const float* __restrict__ csr_v,
                                 const float* __restrict__ bias,
                                 float* __restrict__ agg) {
    const int warp = threadIdx.x >> 5;
    const int lane = threadIdx.x & 31;
    const int d    = blockIdx.x * 8 + warp;
    if (d >= N_NODES) return;
    const int beg = __ldg(off + d);
    const int end = __ldg(off + d + 1);

    const float4* S4 = reinterpret_cast<const float4*>(S);
    float4 b = __ldg(reinterpret_cast<const float4*>(bias) + lane);
    float ax = b.x, ay = b.y, az = b.z, aw = b.w;

    int i = beg;
    for (; i + 4 <= end; i += 4) {
        const int   s0 = __ldg(csr_s + i),     s1 = __ldg(csr_s + i + 1);
        const int   s2 = __ldg(csr_s + i + 2), s3 = __ldg(csr_s + i + 3);
        const float v0 = __ldg(csr_v + i),     v1 = __ldg(csr_v + i + 1);
        const float v2 = __ldg(csr_v + i + 2), v3 = __ldg(csr_v + i + 3);
        const float4 x0 = __ldg(S4 + (size_t)s0 * 32 + lane);
        const float4 x1 = __ldg(S4 + (size_t)s1 * 32 + lane);
        const float4 x2 = __ldg(S4 + (size_t)s2 * 32 + lane);
        const float4 x3 = __ldg(S4 + (size_t)s3 * 32 + lane);
        ax += v0 * x0.x + v1 * x1.x + v2 * x2.x + v3 * x3.x;
        ay += v0 * x0.y + v1 * x1.y + v2 * x2.y + v3 * x3.y;
        az += v0 * x0.z + v1 * x1.z + v2 * x2.z + v3 * x3.z;
        aw += v0 * x0.w + v1 * x1.w + v2 * x2.w + v3 * x3.w;
    }
    for (; i < end; i++) {
        const float v = __ldg(csr_v + i);
        const float4 x = __ldg(S4 + (size_t)__ldg(csr_s + i) * 32 + lane);
        ax += v * x.x; ay += v * x.y; az += v * x.z; aw += v * x.w;
    }
    reinterpret_cast<float4*>(agg)[(size_t)d * 32 + lane] = make_float4(ax, ay, az, aw);
}

// ---------------------------------------------------------------------------
// Pull-mode aggregation, F = 40: one block (64 thr, 40 active) per node.
// ---------------------------------------------------------------------------
__global__ void gather40_kernel(const float* __restrict__ S,
                                const int* __restrict__ off,
                                const int* __restrict__ csr_s,
                                const float* __restrict__ csr_v,
                                const float* __restrict__ bias,
                                float* __restrict__ agg) {
    const int d = blockIdx.x;
    const int t = threadIdx.x;
    if (t >= NCLASS) return;
    const int beg = __ldg(off + d);
    const int end = __ldg(off + d + 1);
    float acc = __ldg(bias + t);
    int i = beg;
    for (; i + 4 <= end; i += 4) {
        const int   s0 = __ldg(csr_s + i),     s1 = __ldg(csr_s + i + 1);
        const int   s2 = __ldg(csr_s + i + 2), s3 = __ldg(csr_s + i + 3);
        const float v0 = __ldg(csr_v + i),     v1 = __ldg(csr_v + i + 1);
        const float v2 = __ldg(csr_v + i + 2), v3 = __ldg(csr_v + i + 3);
        const float x0 = __ldg(S + (size_t)s0 * NCLASS + t);
        const float x1 = __ldg(S + (size_t)s1 * NCLASS + t);
        const float x2 = __ldg(S + (size_t)s2 * NCLASS + t);
        const float x3 = __ldg(S + (size_t)s3 * NCLASS + t);
        acc += v0 * x0 + v1 * x1 + v2 * x2 + v3 * x3;
    }
    for (; i < end; i++)
        acc += __ldg(csr_v + i) * __ldg(S + (size_t)__ldg(csr_s + i) * NCLASS + t);
    agg[(size_t)d * NCLASS + t] = acc;
}

// ---------------------------------------------------------------------------
// In-place log_softmax over 40 classes (bias already baked in): warp per row.
// ---------------------------------------------------------------------------
__global__ void logsoftmax_kernel(float* __restrict__ out) {
    const int warp = threadIdx.x >> 5;
    const int lane = threadIdx.x & 31;
    const int row  = blockIdx.x * 8 + warp;
    if (row >= N_NODES) return;
    float* p = out + (size_t)row * NCLASS;

    const float NEG_INF = __int_as_float(0xff800000);
    float v0 = p[lane];
    float v1 = (lane < 8) ? p[32 + lane] : NEG_INF;

    float m = fmaxf(v0, v1);
    #pragma unroll
    for (int o = 16; o; o >>= 1) m = fmaxf(m, __shfl_xor_sync(0xffffffffu, m, o));

    float s = expf(v0 - m) + ((lane < 8) ? expf(v1 - m) : 0.f);
    #pragma unroll
    for (int o = 16; o; o >>= 1) s += __shfl_xor_sync(0xffffffffu, s, o);

    const float ls = m + logf(s);
    p[lane] = v0 - ls;
    if (lane < 8) p[32 + lane] = v1 - ls;
}

// ---------------------------------------------------------------------------
extern "C" void kernel_launch(void* const* d_in, const int* in_sizes, int n_in,
                              void* d_out, int out_size) {
    const float* x    = (const float*)d_in[0];
    const int*   esrc = (const int*)  d_in[1];
    const int*   edst = (const int*)  d_in[2];
    const float* ev   = (const float*)d_in[3];
    const float* W1   = (const float*)d_in[4];
    const float* b1   = (const float*)d_in[5];
    const float* W2   = (const float*)d_in[6];
    const float* b2   = (const float*)d_in[7];
    const float* W3   = (const float*)d_in[8];
    const float* b3   = (const float*)d_in[9];
    float* out = (float*)d_out;

    float *bufA, *bufB, *bufC, *csrV;
    int *deg, *off, *cursor, *bsum, *csrS;
    cudaGetSymbolAddress((void**)&bufA,   g_bufA);
    cudaGetSymbolAddress((void**)&bufB,   g_bufB);
    cudaGetSymbolAddress((void**)&bufC,   g_bufC);
    cudaGetSymbolAddress((void**)&deg,    g_deg);
    cudaGetSymbolAddress((void**)&off,    g_off);
    cudaGetSymbolAddress((void**)&cursor, g_cursor);
    cudaGetSymbolAddress((void**)&bsum,   g_bsum);
    cudaGetSymbolAddress((void**)&csrS,   g_csr_src);
    cudaGetSymbolAddress((void**)&csrV,   g_csr_val);

    const int edge_blocks = (N_EDGES + 255) / 256;
    const int gemm_blocks = (N_NODES + 127) / 128;           // 782

    // ---- Build CSR by destination (reused by all 3 layers) ----
    cudaMemsetAsync(deg, 0, N_NODES * sizeof(int));
    hist_kernel<<<edge_blocks, 256>>>(edst, deg);
    scan_block_kernel<<<NB, SCAN_BS>>>(deg, off, bsum);
    scan_sums_kernel<<<1, 128>>>(bsum);
    scan_add2_kernel<<<(N_NODES + 255) / 256, 256>>>(off, bsum);
    cudaMemcpyAsync(cursor, off, N_NODES * sizeof(int), cudaMemcpyDeviceToDevice);
    csr_fill_kernel<<<edge_blocks, 256>>>(esrc, edst, ev, cursor, csrS, csrV);

    // ---- Layer 1 ----
    gemm_tc_kernel<NFEAT, false><<<gemm_blocks, 256>>>(x, W1, bufA);
    gather128_kernel<<<(N_NODES + 7) / 8, 256>>>(bufA, off, csrS, csrV, b1, bufB);

    // ---- Layer 2 ----
    gemm_tc_kernel<NHID, true><<<gemm_blocks, 256>>>(bufB, W2, bufA);
    gather128_kernel<<<(N_NODES + 7) / 8, 256>>>(bufA, off, csrS, csrV, b2, bufB);

    // ---- Layer 3 ----
    gemm_small_kernel<NHID, NCLASS, 8, 2, true><<<N_NODES / 16, dim3(NCLASS, 8)>>>(bufB, W3, bufC);
    gather40_kernel<<<N_NODES, 64>>>(bufC, off, csrS, csrV, b3, out);
    logsoftmax_kernel<<<(N_NODES + 7) / 8, 256>>>(out);
}